// round 13
// baseline (speedup 1.0000x reference)
#include <cuda_runtime.h>
#include <cuda_bf16.h>
#include <cstdint>

// ---------------- static scratch ----------------
#define MAXE (4 * 50000 * 64)
static __device__ __align__(16) float g_xbuf[MAXE];      // activations [B,F,C]
static __device__ __align__(16) float g_ybuf[MAXE];      // raw conv out [B,F,64]
// bf16 weight fragments: [sel][chunk g][split][p][lane][4 u32]
static __device__ __align__(16) uint32_t g_wfrag[3][16 * 1024];
static __device__ __align__(16) float g_psum[3200 * 64];
static __device__ __align__(16) float g_psumsq[3200 * 64];
static __device__ __align__(16) float g_p2S[64 * 64];
static __device__ __align__(16) float g_p2Q[64 * 64];
static __device__ __align__(16) float g_coefA[3 * 64];
static __device__ __align__(16) float g_coefS[3 * 64];

__device__ __forceinline__ float lrelu(float v) { return v >= 0.f ? v : 0.2f * v; }

__device__ __forceinline__ uint32_t s2u(const void* p) {
    uint32_t a;
    asm("{ .reg .u64 t; cvta.to.shared.u64 t, %1; cvt.u32.u64 %0, t; }" : "=r"(a) : "l"(p));
    return a;
}
__device__ __forceinline__ void cpa16(uint32_t dst, const void* src) {
    asm volatile("cp.async.cg.shared.global [%0], [%1], 16;" :: "r"(dst), "l"(src));
}
#define CPA_COMMIT() asm volatile("cp.async.commit_group;" ::: "memory")
#define CPA_WAIT2()  asm volatile("cp.async.wait_group 2;" ::: "memory")

// MMA: D += A(bf16) * B(bf16), m16n8k16, fp32 accum
#define MMA16(dd, aa, b0, b1)                                                   \
    asm volatile(                                                               \
        "mma.sync.aligned.m16n8k16.row.col.f32.bf16.bf16.f32 "                  \
        "{%0,%1,%2,%3},{%4,%5,%6,%7},{%8,%9},{%0,%1,%2,%3};"                    \
        : "+f"(dd[0]), "+f"(dd[1]), "+f"(dd[2]), "+f"(dd[3])                    \
        : "r"(aa[0]), "r"(aa[1]), "r"(aa[2]), "r"(aa[3]), "r"(b0), "r"(b1))

#define LDSM4(rr, addr)                                                         \
    asm volatile("ldmatrix.sync.aligned.m8n8.x4.shared.b16 {%0,%1,%2,%3}, [%4];"\
        : "=r"(rr[0]), "=r"(rr[1]), "=r"(rr[2]), "=r"(rr[3]) : "r"(addr))

__device__ __forceinline__ uint32_t packbf2(float a, float b) {
    __nv_bfloat162 h = __floats2bfloat162_rn(a, b);
    return *reinterpret_cast<uint32_t*>(&h);
}

// ---------------- weight prep: bf16 hi/lo fragment order ----------------
__global__ void k_wprep_all(const float* __restrict__ w1,
                            const float* __restrict__ w2a,
                            const float* __restrict__ w2b, int K1) {
    int i = blockIdx.x * 256 + threadIdx.x;
    int n1 = K1 * 64;
    const float* w;
    int sel, K, idx;
    if (i < n1) { w = w1; sel = 0; K = K1; idx = i; }
    else if (i < n1 + 16384) { w = w2a; sel = 1; K = 256; idx = i - n1; }
    else if (i < n1 + 32768) { w = w2b; sel = 2; K = 256; idx = i - n1 - 16384; }
    else return;
    int wq = idx & 3, lane = (idx >> 2) & 31, p = (idx >> 7) & 3,
        split = (idx >> 9) & 1, g = idx >> 10;
    int r = lane >> 2, c = lane & 3;
    int n = p * 2 + (wq >> 1), j = wq & 1;
    int k0 = g * 16 + 2 * c + 8 * j;
    int o = n * 8 + r;
    float x0 = w[o * K + k0], x1 = w[o * K + k0 + 1];
    __nv_bfloat16 h0 = __float2bfloat16_rn(x0);
    __nv_bfloat16 h1 = __float2bfloat16_rn(x1);
    uint32_t val;
    if (split == 0) {
        __nv_bfloat162 hh; hh.x = h0; hh.y = h1;
        val = *reinterpret_cast<uint32_t*>(&hh);
    } else {
        val = packbf2(x0 - __bfloat162float(h0), x1 - __bfloat162float(h1));
    }
    g_wfrag[sel][(size_t)g * 1024 + split * 512 + p * 128 + lane * 4 + wq] = val;
}

// ---------------- transpose fe [B,C,F] -> g_xbuf [B,F,C] (half batch) ----------------
__global__ void k_transpose(const float* __restrict__ fe, int C, int F, int b0) {
    __shared__ float sm[32][33];
    int b = b0 + blockIdx.z;
    int f0 = blockIdx.x * 32;
    int tx = threadIdx.x, ty = threadIdx.y;
#pragma unroll
    for (int r = 0; r < 4; r++) {
        int c = ty + r * 8;
        int f = f0 + tx;
        float v = 0.f;
        if (f < F && c < C) v = fe[((size_t)b * C + c) * F + f];
        sm[c][tx] = v;
    }
    __syncthreads();
#pragma unroll
    for (int r = 0; r < 4; r++) {
        int f = f0 + ty + r * 8;
        int c = tx;
        if (f < F && c < C) g_xbuf[((size_t)b * F + f) * C + c] = sm[c][ty + r * 8];
    }
}

// ---------------- fused gather + feature build + bf16 MMA GEMM ----------------
// Tile 128 faces x 64 out, 128 thr = 4 warps. A warp-local, raw gather
// thread-local, B direct from global (L1-resident). Barrier-free mainloop;
// 3-deep cp.async raw prefetch (wait_group 2, 4 banks).
template <int CIN>
__global__ __launch_bounds__(128, 4) void k_conv(const int* __restrict__ gidx,
                                                 int wsel,
                                                 const float* __restrict__ bias,
                                                 int F) {
    constexpr int NG = CIN / 4;                // 16-k chunks
    constexpr int OFF_GH = 0;                  // 2 x 4096 (A hi)
    constexpr int OFF_GL = 8192;               // 2 x 4096 (A lo)
    constexpr int OFF_RAW = 16384;             // 4 x 8192
    constexpr int OFF_SIDX = 49152;            // [128][3] int
    constexpr int OFF_BIAS = 50688;            // 64 f32

    extern __shared__ char smc[];
    uint32_t sb = s2u(smc);
    int* sidx = (int*)(smc + OFF_SIDX);
    float* bias_s = (float*)(smc + OFF_BIAS);

    int t = threadIdx.x;
    int warp = t >> 5, lane = t & 31;
    int r = lane >> 2, c = lane & 3;
    int q = lane >> 3;
    int b = blockIdx.y;
    int f0 = blockIdx.x * 128;
    int nv = F - f0; if (nv > 128) nv = 128;

    if (t < 64) bias_s[t] = __ldg(&bias[t]);
    for (int i = t; i < 128 * 3; i += 128) {
        int fi = i / 3, j = i - fi * 3;
        sidx[i] = (f0 + fi < F) ? __ldg(&gidx[((size_t)b * F + f0 + fi) * 3 + j]) : 0;
    }
    __syncthreads();

    int fc = f0 + (t < nv ? t : (nv - 1));
    const float* s0 = &g_xbuf[((size_t)b * F + fc) * CIN];
    const float* s1 = &g_xbuf[((size_t)b * F + sidx[t * 3 + 0]) * CIN];
    const float* s2 = &g_xbuf[((size_t)b * F + sidx[t * 3 + 1]) * CIN];
    const float* s3 = &g_xbuf[((size_t)b * F + sidx[t * 3 + 2]) * CIN];
    const uint32_t* wfr = g_wfrag[wsel];
    bool fv = t < nv;

    // ldmatrix per-thread row address (invariant part)
    uint32_t aoff = (uint32_t)((warp * 4 + (q & 1)) * 256 + (q >> 1) * 128 + (lane & 7) * 16);

    auto ISSUE = [&](int g) {
        if (g < NG) {
            uint32_t rb = sb + OFF_RAW + (uint32_t)(g & 3) * 8192 + t * 16;
            cpa16(rb, s0 + g * 4);
            cpa16(rb + 2048, s1 + g * 4);
            cpa16(rb + 4096, s2 + g * 4);
            cpa16(rb + 6144, s3 + g * 4);
        }
        CPA_COMMIT();   // empty group beyond NG keeps per-thread counts aligned
    };

    auto CONVERT = [&](int g) {
        int buf = g & 1;
        const float4* rp = (const float4*)(smc + OFF_RAW + (uint32_t)(g & 3) * 8192);
        float4 vc = rp[t], v1 = rp[128 + t], v2 = rp[256 + t], v3 = rp[384 + t];
        const float* pc = (const float*)&vc;
        const float* p1 = (const float*)&v1;
        const float* p2 = (const float*)&v2;
        const float* p3 = (const float*)&v3;
        float f[16];
#pragma unroll
        for (int cc = 0; cc < 4; cc++) {
            float x1 = p1[cc], x2 = p2[cc], x3 = p3[cc];
            f[cc * 4 + 0] = fv ? pc[cc] : 0.f;
            f[cc * 4 + 1] = fv ? (x1 + x2 + x3) : 0.f;
            f[cc * 4 + 2] = fv ? (fabsf(x1 - x2) + fabsf(x2 - x3) + fabsf(x3 - x1)) : 0.f;
            f[cc * 4 + 3] = fv ? fmaxf(x1, fmaxf(x2, x3)) : 0.f;
        }
        uint32_t hiw[8], low[8];
#pragma unroll
        for (int kp = 0; kp < 8; kp++) {
            float x0 = f[2 * kp], x1 = f[2 * kp + 1];
            __nv_bfloat16 h0 = __float2bfloat16_rn(x0);
            __nv_bfloat16 h1 = __float2bfloat16_rn(x1);
            __nv_bfloat162 hh; hh.x = h0; hh.y = h1;
            hiw[kp] = *reinterpret_cast<uint32_t*>(&hh);
            low[kp] = packbf2(x0 - __bfloat162float(h0), x1 - __bfloat162float(h1));
        }
        uint32_t rowoff = (uint32_t)((t >> 3) * 256 + (t & 7) * 16);
        char* gh = smc + OFF_GH + buf * 4096 + rowoff;
        char* gl = smc + OFF_GL + buf * 4096 + rowoff;
        *(uint4*)gh = make_uint4(hiw[0], hiw[1], hiw[2], hiw[3]);
        *(uint4*)(gh + 128) = make_uint4(hiw[4], hiw[5], hiw[6], hiw[7]);
        *(uint4*)gl = make_uint4(low[0], low[1], low[2], low[3]);
        *(uint4*)(gl + 128) = make_uint4(low[4], low[5], low[6], low[7]);
    };

    float d[2][8][4];
#pragma unroll
    for (int m = 0; m < 2; m++)
#pragma unroll
        for (int n = 0; n < 8; n++)
#pragma unroll
            for (int qq = 0; qq < 4; qq++) d[m][n][qq] = 0.f;

    auto GEMM = [&](int g) {
        // B fragments direct from global (L1-resident; coalesced per-lane layout)
        const uint4* wg = (const uint4*)(wfr + (size_t)g * 1024 + lane * 4);
        uint4 hv[4], lv[4];
#pragma unroll
        for (int p = 0; p < 4; p++) {
            hv[p] = __ldg(wg + p * 32);
            lv[p] = __ldg(wg + 128 + p * 32);
        }
        const uint32_t* bh = (const uint32_t*)hv;
        const uint32_t* bl = (const uint32_t*)lv;
        int buf = g & 1;
#pragma unroll
        for (int mt = 0; mt < 2; mt++) {
            uint32_t ah[4], al[4];
            uint32_t addr = sb + (uint32_t)(mt * 512) + aoff;
            LDSM4(ah, addr + OFF_GH + buf * 4096);
            LDSM4(al, addr + OFF_GL + buf * 4096);
#pragma unroll
            for (int n = 0; n < 8; n++) {
                MMA16(d[mt][n], ah, bh[n * 2], bh[n * 2 + 1]);
                MMA16(d[mt][n], ah, bl[n * 2], bl[n * 2 + 1]);
                MMA16(d[mt][n], al, bh[n * 2], bh[n * 2 + 1]);
            }
        }
    };

    // barrier-free per-warp pipeline, 3-deep raw prefetch
    ISSUE(0); ISSUE(1); ISSUE(2);
    CPA_WAIT2();          // chunk 0 arrived
    CONVERT(0);
    __syncwarp();
#pragma unroll 1
    for (int g = 0; g < NG; g++) {
        ISSUE(g + 3);
        GEMM(g);
        CPA_WAIT2();      // chunk g+1 arrived (issued 2 bodies ago)
        if (g + 1 < NG) { CONVERT(g + 1); __syncwarp(); }
    }

    // epilogue: bias, store y [B,F,64], per-block deterministic sums
    int m0 = warp * 32;
    float ls[16], lq2[16];
#pragma unroll
    for (int i = 0; i < 16; i++) { ls[i] = 0.f; lq2[i] = 0.f; }
#pragma unroll
    for (int m = 0; m < 2; m++) {
        int fA = m0 + m * 16 + r;
        int fB = fA + 8;
#pragma unroll
        for (int n = 0; n < 8; n++) {
            int c0 = n * 8 + 2 * c;
            float b0 = bias_s[c0], b1 = bias_s[c0 + 1];
            float v00 = d[m][n][0] + b0, v01 = d[m][n][1] + b1;
            float v10 = d[m][n][2] + b0, v11 = d[m][n][3] + b1;
            if (fA < nv) {
                *(float2*)&g_ybuf[((size_t)b * F + f0 + fA) * 64 + c0] = make_float2(v00, v01);
                ls[n * 2] += v00; lq2[n * 2] += v00 * v00;
                ls[n * 2 + 1] += v01; lq2[n * 2 + 1] += v01 * v01;
            }
            if (fB < nv) {
                *(float2*)&g_ybuf[((size_t)b * F + f0 + fB) * 64 + c0] = make_float2(v10, v11);
                ls[n * 2] += v10; lq2[n * 2] += v10 * v10;
                ls[n * 2 + 1] += v11; lq2[n * 2 + 1] += v11 * v11;
            }
        }
    }
    __syncthreads();   // all warps done with A smem before reuse as reduction space
    float* redS = (float*)(smc);            // [32][64]
    float* redQ = (float*)(smc + 8192);
    int row = warp * 8 + r;
#pragma unroll
    for (int n = 0; n < 8; n++) {
        redS[row * 64 + n * 8 + 2 * c] = ls[n * 2];
        redS[row * 64 + n * 8 + 2 * c + 1] = ls[n * 2 + 1];
        redQ[row * 64 + n * 8 + 2 * c] = lq2[n * 2];
        redQ[row * 64 + n * 8 + 2 * c + 1] = lq2[n * 2 + 1];
    }
    __syncthreads();
    if (t < 64) {
        float s = 0.f, q2 = 0.f;
#pragma unroll 8
        for (int i = 0; i < 32; i++) { s += redS[i * 64 + t]; q2 += redQ[i * 64 + t]; }
        int bid = blockIdx.y * gridDim.x + blockIdx.x;
        g_psum[bid * 64 + t] = s;
        g_psumsq[bid * 64 + t] = q2;
    }
}

// ---------------- reduction level 1: nblk partial rows -> 64 rows ----------------
__global__ void k_red1(int nblk, int rpb) {
    __shared__ float sS[4][64], sQ[4][64];
    int t = threadIdx.x;
    int c = t & 63, sl = t >> 6;
    int r0 = blockIdx.x * rpb;
    int r1 = r0 + rpb; if (r1 > nblk) r1 = nblk;
    float s = 0.f, q = 0.f;
    for (int i = r0 + sl; i < r1; i += 4) {
        s += g_psum[i * 64 + c];
        q += g_psumsq[i * 64 + c];
    }
    sS[sl][c] = s; sQ[sl][c] = q;
    __syncthreads();
    if (t < 64) {
        g_p2S[blockIdx.x * 64 + t] = sS[0][t] + sS[1][t] + sS[2][t] + sS[3][t];
        g_p2Q[blockIdx.x * 64 + t] = sQ[0][t] + sQ[1][t] + sQ[2][t] + sQ[3][t];
    }
}

// ---------------- apply with fused coefficient computation ----------------
__global__ __launch_bounds__(256) void k_applyc(const float* __restrict__ gamma,
                                                const float* __restrict__ beta,
                                                float invN, int res, int nvec) {
    __shared__ float sS[4][64], sQ[4][64];
    __shared__ float cA[64], cS[64];
    int t = threadIdx.x;
    int c = t & 63, sl = t >> 6;
    float s = 0.f, q = 0.f;
#pragma unroll
    for (int i = sl; i < 64; i += 4) {
        s += g_p2S[i * 64 + c];
        q += g_p2Q[i * 64 + c];
    }
    sS[sl][c] = s; sQ[sl][c] = q;
    __syncthreads();
    if (t < 64) {
        float ss = sS[0][t] + sS[1][t] + sS[2][t] + sS[3][t];
        float qq = sQ[0][t] + sQ[1][t] + sQ[2][t] + sQ[3][t];
        float m = ss * invN;
        float var = qq * invN - m * m;
        float rstd = rsqrtf(var + 1e-5f);
        float a = gamma[t] * rstd;
        cA[t] = a;
        cS[t] = beta[t] - m * a;
    }
    __syncthreads();
#pragma unroll
    for (int it = 0; it < 8; it++) {
        int i = (blockIdx.x * 8 + it) * 256 + t;
        if (i >= nvec) break;
        int c4 = i & 15;
        float4 a = *(const float4*)&cA[c4 * 4];
        float4 sh = *(const float4*)&cS[c4 * 4];
        float4 yv = ((const float4*)g_ybuf)[i];
        float4 o;
        o.x = a.x * yv.x + sh.x; o.y = a.y * yv.y + sh.y;
        o.z = a.z * yv.z + sh.z; o.w = a.w * yv.w + sh.w;
        if (res) {
            float4 xv = ((const float4*)g_xbuf)[i];
            o.x += xv.x; o.y += xv.y; o.z += xv.z; o.w += xv.w;
        }
        o.x = lrelu(o.x); o.y = lrelu(o.y); o.z = lrelu(o.z); o.w = lrelu(o.w);
        ((float4*)g_xbuf)[i] = o;
    }
}

// ---------------- coef finalize (stage 2 only) ----------------
__global__ void k_coef(const float* __restrict__ gamma,
                       const float* __restrict__ beta, int stage, float invN) {
    __shared__ float sS[4][64], sQ[4][64];
    int t = threadIdx.x;
    int c = t & 63, sl = t >> 6;
    float s = 0.f, q = 0.f;
#pragma unroll
    for (int i = sl; i < 64; i += 4) {
        s += g_p2S[i * 64 + c];
        q += g_p2Q[i * 64 + c];
    }
    sS[sl][c] = s; sQ[sl][c] = q;
    __syncthreads();
    if (t < 64) {
        float ss = sS[0][t] + sS[1][t] + sS[2][t] + sS[3][t];
        float qq = sQ[0][t] + sQ[1][t] + sQ[2][t] + sQ[3][t];
        float m = ss * invN;
        float var = qq * invN - m * m;
        float rstd = rsqrtf(var + 1e-5f);
        float a = gamma[t] * rstd;
        g_coefA[stage * 64 + t] = a;
        g_coefS[stage * 64 + t] = beta[t] - m * a;
    }
}

// ---------------- final apply + transpose to [B,O,F] ----------------
__global__ void k_apply_out(float* __restrict__ out, int F) {
    __shared__ float sm[32][33];
    int b = blockIdx.z;
    int o0 = blockIdx.y * 32;
    int f0 = blockIdx.x * 32;
    int tx = threadIdx.x, ty = threadIdx.y;
#pragma unroll
    for (int r = 0; r < 4; r++) {
        int f = f0 + ty + r * 8;
        int o = o0 + tx;
        float v = 0.f;
        if (f < F) {
            float a = g_coefA[2 * 64 + o], s = g_coefS[2 * 64 + o];
            size_t idx = ((size_t)b * F + f) * 64 + o;
            v = lrelu(a * g_ybuf[idx] + s + g_xbuf[idx]);
        }
        sm[ty + r * 8][tx] = v;
    }
    __syncthreads();
#pragma unroll
    for (int r = 0; r < 4; r++) {
        int o = o0 + ty + r * 8;
        int f = f0 + tx;
        if (f < F) out[((size_t)b * 64 + o) * F + f] = sm[tx][ty + r * 8];
    }
}

// ---------------- host launcher ----------------
extern "C" void kernel_launch(void* const* d_in, const int* in_sizes, int n_in,
                              void* d_out, int out_size) {
    const float* fe  = (const float*)d_in[0];
    const int*   gm  = (const int*)d_in[1];
    const float* w1  = (const float*)d_in[2];
    const float* b1  = (const float*)d_in[3];
    const float* w2a = (const float*)d_in[4];
    const float* b2a = (const float*)d_in[5];
    const float* w2b = (const float*)d_in[6];
    const float* b2b = (const float*)d_in[7];
    const float* g0  = (const float*)d_in[8];
    const float* be0 = (const float*)d_in[9];
    const float* g1  = (const float*)d_in[10];
    const float* be1 = (const float*)d_in[11];
    const float* g2  = (const float*)d_in[12];
    const float* be2 = (const float*)d_in[13];

    const int B = 4;
    const int F = in_sizes[1] / (3 * B);      // 50000
    const int Cin = in_sizes[0] / (B * F);    // 32

    const int SH = 50944;
    cudaFuncSetAttribute(k_conv<32>, cudaFuncAttributeMaxDynamicSharedMemorySize, SH);
    cudaFuncSetAttribute(k_conv<64>, cudaFuncAttributeMaxDynamicSharedMemorySize, SH);

    dim3 tb(32, 8);
    int ftiles32 = (F + 31) / 32;
    int fb = (F + 127) / 128;
    int nblk = fb * B;
    int rpb = (nblk + 63) / 64;
    float invN = 1.0f / (float)(B * F);
    int nvec = B * F * 16;
    int apb = (nvec + 2047) / 2048;
    int K1 = 4 * Cin;

    // launch order: conv<32> is my 4th launch -> captured by ncu
    k_wprep_all<<<(K1 * 64 + 32768 + 255) / 256, 256>>>(w1, w2a, w2b, K1);   // 1
    k_transpose<<<dim3(ftiles32, 1, 2), tb>>>(fe, Cin, F, 0);                // 2
    k_transpose<<<dim3(ftiles32, 1, 2), tb>>>(fe, Cin, F, 2);                // 3

    // stage 0
    k_conv<32><<<dim3(fb, B), 128, SH>>>(gm, 0, b1, F);                      // 4 <- ncu
    k_red1<<<64, 256>>>(nblk, rpb);
    k_applyc<<<apb, 256>>>(g0, be0, invN, 0, nvec);

    // stage 1 (residual)
    k_conv<64><<<dim3(fb, B), 128, SH>>>(gm, 1, b2a, F);
    k_red1<<<64, 256>>>(nblk, rpb);
    k_applyc<<<apb, 256>>>(g1, be1, invN, 1, nvec);

    // stage 2 (residual, fused final transpose)
    k_conv<64><<<dim3(fb, B), 128, SH>>>(gm, 2, b2b, F);
    k_red1<<<64, 256>>>(nblk, rpb);
    k_coef<<<1, 256>>>(g2, be2, 2, invN);
    k_apply_out<<<dim3(ftiles32, 2, B), tb>>>((float*)d_out, F);
}

// round 14
// speedup vs baseline: 1.0313x; 1.0313x over previous
#include <cuda_runtime.h>
#include <cuda_bf16.h>
#include <cstdint>

// ---------------- static scratch ----------------
#define MAXE (4 * 50000 * 64)
static __device__ __align__(16) float g_xbuf[MAXE];      // activations [B,F,C]
static __device__ __align__(16) float g_ybuf[MAXE];      // raw conv out [B,F,64]
// bf16 weight fragments: [sel][chunk g][split][p][lane][4 u32]
static __device__ __align__(16) uint32_t g_wfrag[3][16 * 1024];
static __device__ __align__(16) float g_psum[3200 * 64];
static __device__ __align__(16) float g_psumsq[3200 * 64];
static __device__ __align__(16) float g_p2S[64 * 64];
static __device__ __align__(16) float g_p2Q[64 * 64];
static __device__ __align__(16) float g_coefA[3 * 64];
static __device__ __align__(16) float g_coefS[3 * 64];

__device__ __forceinline__ float lrelu(float v) { return v >= 0.f ? v : 0.2f * v; }

__device__ __forceinline__ uint32_t s2u(const void* p) {
    uint32_t a;
    asm("{ .reg .u64 t; cvta.to.shared.u64 t, %1; cvt.u32.u64 %0, t; }" : "=r"(a) : "l"(p));
    return a;
}
__device__ __forceinline__ void cpa16(uint32_t dst, const void* src) {
    asm volatile("cp.async.cg.shared.global [%0], [%1], 16;" :: "r"(dst), "l"(src));
}
#define CPA_COMMIT() asm volatile("cp.async.commit_group;" ::: "memory")
#define CPA_WAIT1()  asm volatile("cp.async.wait_group 1;" ::: "memory")

// MMA: D += A(bf16) * B(bf16), m16n8k16, fp32 accum.
// NOT volatile: pure register dataflow -> ptxas may schedule/interleave freely.
#define MMA16(dd, aa, b0, b1)                                                   \
    asm("mma.sync.aligned.m16n8k16.row.col.f32.bf16.bf16.f32 "                  \
        "{%0,%1,%2,%3},{%4,%5,%6,%7},{%8,%9},{%0,%1,%2,%3};"                    \
        : "+f"(dd[0]), "+f"(dd[1]), "+f"(dd[2]), "+f"(dd[3])                    \
        : "r"(aa[0]), "r"(aa[1]), "r"(aa[2]), "r"(aa[3]), "r"(b0), "r"(b1))

#define LDSM4(rr, addr)                                                         \
    asm volatile("ldmatrix.sync.aligned.m8n8.x4.shared.b16 {%0,%1,%2,%3}, [%4];"\
        : "=r"(rr[0]), "=r"(rr[1]), "=r"(rr[2]), "=r"(rr[3]) : "r"(addr))

__device__ __forceinline__ uint32_t packbf2(float a, float b) {
    __nv_bfloat162 h = __floats2bfloat162_rn(a, b);
    return *reinterpret_cast<uint32_t*>(&h);
}

// ---------------- weight prep: bf16 hi/lo fragment order ----------------
__global__ void k_wprep_all(const float* __restrict__ w1,
                            const float* __restrict__ w2a,
                            const float* __restrict__ w2b, int K1) {
    int i = blockIdx.x * 256 + threadIdx.x;
    int n1 = K1 * 64;
    const float* w;
    int sel, K, idx;
    if (i < n1) { w = w1; sel = 0; K = K1; idx = i; }
    else if (i < n1 + 16384) { w = w2a; sel = 1; K = 256; idx = i - n1; }
    else if (i < n1 + 32768) { w = w2b; sel = 2; K = 256; idx = i - n1 - 16384; }
    else return;
    int wq = idx & 3, lane = (idx >> 2) & 31, p = (idx >> 7) & 3,
        split = (idx >> 9) & 1, g = idx >> 10;
    int r = lane >> 2, c = lane & 3;
    int n = p * 2 + (wq >> 1), j = wq & 1;
    int k0 = g * 16 + 2 * c + 8 * j;
    int o = n * 8 + r;
    float x0 = w[o * K + k0], x1 = w[o * K + k0 + 1];
    __nv_bfloat16 h0 = __float2bfloat16_rn(x0);
    __nv_bfloat16 h1 = __float2bfloat16_rn(x1);
    uint32_t val;
    if (split == 0) {
        __nv_bfloat162 hh; hh.x = h0; hh.y = h1;
        val = *reinterpret_cast<uint32_t*>(&hh);
    } else {
        val = packbf2(x0 - __bfloat162float(h0), x1 - __bfloat162float(h1));
    }
    g_wfrag[sel][(size_t)g * 1024 + split * 512 + p * 128 + lane * 4 + wq] = val;
}

// ---------------- transpose fe [B,C,F] -> g_xbuf [B,F,C] (half batch) ----------------
__global__ void k_transpose(const float* __restrict__ fe, int C, int F, int b0) {
    __shared__ float sm[32][33];
    int b = b0 + blockIdx.z;
    int f0 = blockIdx.x * 32;
    int tx = threadIdx.x, ty = threadIdx.y;
#pragma unroll
    for (int r = 0; r < 4; r++) {
        int c = ty + r * 8;
        int f = f0 + tx;
        float v = 0.f;
        if (f < F && c < C) v = fe[((size_t)b * C + c) * F + f];
        sm[c][tx] = v;
    }
    __syncthreads();
#pragma unroll
    for (int r = 0; r < 4; r++) {
        int f = f0 + ty + r * 8;
        int c = tx;
        if (f < F && c < C) g_xbuf[((size_t)b * F + f) * C + c] = sm[c][ty + r * 8];
    }
}

// ---------------- fused gather + feature build + bf16 MMA GEMM ----------------
// Tile 128 faces x 64 out, 128 thr = 4 warps. A warp-local, raw gather
// thread-local, B direct from global (L1-resident). Barrier-free mainloop,
// 2-deep cp.async raw prefetch. MMAs grouped by term (8 independent per group)
// so accumulator RAW chains are 8 issues apart.
template <int CIN>
__global__ __launch_bounds__(128, 4) void k_conv(const int* __restrict__ gidx,
                                                 int wsel,
                                                 const float* __restrict__ bias,
                                                 int F) {
    constexpr int NG = CIN / 4;                // 16-k chunks
    constexpr int OFF_GH = 0;                  // 2 x 4096 (A hi)
    constexpr int OFF_GL = 8192;               // 2 x 4096 (A lo)
    constexpr int OFF_RAW = 16384;             // 2 x 8192
    constexpr int OFF_SIDX = 32768;            // [128][3] int
    constexpr int OFF_BIAS = 34304;            // 64 f32

    extern __shared__ char smc[];
    uint32_t sb = s2u(smc);
    int* sidx = (int*)(smc + OFF_SIDX);
    float* bias_s = (float*)(smc + OFF_BIAS);

    int t = threadIdx.x;
    int warp = t >> 5, lane = t & 31;
    int r = lane >> 2, c = lane & 3;
    int q = lane >> 3;
    int b = blockIdx.y;
    int f0 = blockIdx.x * 128;
    int nv = F - f0; if (nv > 128) nv = 128;

    if (t < 64) bias_s[t] = __ldg(&bias[t]);
    for (int i = t; i < 128 * 3; i += 128) {
        int fi = i / 3, j = i - fi * 3;
        sidx[i] = (f0 + fi < F) ? __ldg(&gidx[((size_t)b * F + f0 + fi) * 3 + j]) : 0;
    }
    __syncthreads();

    int fc = f0 + (t < nv ? t : (nv - 1));
    const float* s0 = &g_xbuf[((size_t)b * F + fc) * CIN];
    const float* s1 = &g_xbuf[((size_t)b * F + sidx[t * 3 + 0]) * CIN];
    const float* s2 = &g_xbuf[((size_t)b * F + sidx[t * 3 + 1]) * CIN];
    const float* s3 = &g_xbuf[((size_t)b * F + sidx[t * 3 + 2]) * CIN];
    const uint32_t* wfr = g_wfrag[wsel];
    bool fv = t < nv;

    // ldmatrix per-thread row address (invariant part)
    uint32_t aoff = (uint32_t)((warp * 4 + (q & 1)) * 256 + (q >> 1) * 128 + (lane & 7) * 16);

    auto ISSUE = [&](int g) {
        if (g < NG) {
            uint32_t rb = sb + OFF_RAW + (uint32_t)(g & 1) * 8192 + t * 16;
            cpa16(rb, s0 + g * 4);
            cpa16(rb + 2048, s1 + g * 4);
            cpa16(rb + 4096, s2 + g * 4);
            cpa16(rb + 6144, s3 + g * 4);
        }
        CPA_COMMIT();   // empty group beyond NG keeps per-thread counts aligned
    };

    auto CONVERT = [&](int g) {
        int buf = g & 1;
        const float4* rp = (const float4*)(smc + OFF_RAW + (uint32_t)buf * 8192);
        float4 vc = rp[t], v1 = rp[128 + t], v2 = rp[256 + t], v3 = rp[384 + t];
        const float* pc = (const float*)&vc;
        const float* p1 = (const float*)&v1;
        const float* p2 = (const float*)&v2;
        const float* p3 = (const float*)&v3;
        float f[16];
#pragma unroll
        for (int cc = 0; cc < 4; cc++) {
            float x1 = p1[cc], x2 = p2[cc], x3 = p3[cc];
            f[cc * 4 + 0] = fv ? pc[cc] : 0.f;
            f[cc * 4 + 1] = fv ? (x1 + x2 + x3) : 0.f;
            f[cc * 4 + 2] = fv ? (fabsf(x1 - x2) + fabsf(x2 - x3) + fabsf(x3 - x1)) : 0.f;
            f[cc * 4 + 3] = fv ? fmaxf(x1, fmaxf(x2, x3)) : 0.f;
        }
        uint32_t hiw[8], low[8];
#pragma unroll
        for (int kp = 0; kp < 8; kp++) {
            float x0 = f[2 * kp], x1 = f[2 * kp + 1];
            __nv_bfloat16 h0 = __float2bfloat16_rn(x0);
            __nv_bfloat16 h1 = __float2bfloat16_rn(x1);
            __nv_bfloat162 hh; hh.x = h0; hh.y = h1;
            hiw[kp] = *reinterpret_cast<uint32_t*>(&hh);
            low[kp] = packbf2(x0 - __bfloat162float(h0), x1 - __bfloat162float(h1));
        }
        uint32_t rowoff = (uint32_t)((t >> 3) * 256 + (t & 7) * 16);
        char* gh = smc + OFF_GH + buf * 4096 + rowoff;
        char* gl = smc + OFF_GL + buf * 4096 + rowoff;
        *(uint4*)gh = make_uint4(hiw[0], hiw[1], hiw[2], hiw[3]);
        *(uint4*)(gh + 128) = make_uint4(hiw[4], hiw[5], hiw[6], hiw[7]);
        *(uint4*)gl = make_uint4(low[0], low[1], low[2], low[3]);
        *(uint4*)(gl + 128) = make_uint4(low[4], low[5], low[6], low[7]);
    };

    float d[2][8][4];
#pragma unroll
    for (int m = 0; m < 2; m++)
#pragma unroll
        for (int n = 0; n < 8; n++)
#pragma unroll
            for (int qq = 0; qq < 4; qq++) d[m][n][qq] = 0.f;

    auto GEMM = [&](int g) {
        // B fragments direct from global (L1-resident; coalesced per-lane layout)
        const uint4* wg = (const uint4*)(wfr + (size_t)g * 1024 + lane * 4);
        uint4 hv[4], lv[4];
#pragma unroll
        for (int p = 0; p < 4; p++) {
            hv[p] = __ldg(wg + p * 32);
            lv[p] = __ldg(wg + 128 + p * 32);
        }
        const uint32_t* bh = (const uint32_t*)hv;
        const uint32_t* bl = (const uint32_t*)lv;
        int buf = g & 1;
#pragma unroll
        for (int mt = 0; mt < 2; mt++) {
            uint32_t ah[4], al[4];
            uint32_t addr = sb + (uint32_t)(mt * 512) + aoff;
            LDSM4(ah, addr + OFF_GH + buf * 4096);
            LDSM4(al, addr + OFF_GL + buf * 4096);
            // term-grouped: 8 independent MMAs per group; RAW on d is 8 apart
#pragma unroll
            for (int n = 0; n < 8; n++) MMA16(d[mt][n], ah, bh[n * 2], bh[n * 2 + 1]);
#pragma unroll
            for (int n = 0; n < 8; n++) MMA16(d[mt][n], ah, bl[n * 2], bl[n * 2 + 1]);
#pragma unroll
            for (int n = 0; n < 8; n++) MMA16(d[mt][n], al, bh[n * 2], bh[n * 2 + 1]);
        }
    };

    // barrier-free per-warp pipeline (2-deep raw prefetch)
    ISSUE(0); ISSUE(1);
    CPA_WAIT1();
    CONVERT(0);
    __syncwarp();
#pragma unroll 1
    for (int g = 0; g < NG; g++) {
        ISSUE(g + 2);
        GEMM(g);
        CPA_WAIT1();
        if (g + 1 < NG) { CONVERT(g + 1); __syncwarp(); }
    }

    // epilogue: bias, store y [B,F,64], per-block deterministic sums
    int m0 = warp * 32;
    float ls[16], lq2[16];
#pragma unroll
    for (int i = 0; i < 16; i++) { ls[i] = 0.f; lq2[i] = 0.f; }
#pragma unroll
    for (int m = 0; m < 2; m++) {
        int fA = m0 + m * 16 + r;
        int fB = fA + 8;
#pragma unroll
        for (int n = 0; n < 8; n++) {
            int c0 = n * 8 + 2 * c;
            float b0 = bias_s[c0], b1 = bias_s[c0 + 1];
            float v00 = d[m][n][0] + b0, v01 = d[m][n][1] + b1;
            float v10 = d[m][n][2] + b0, v11 = d[m][n][3] + b1;
            if (fA < nv) {
                *(float2*)&g_ybuf[((size_t)b * F + f0 + fA) * 64 + c0] = make_float2(v00, v01);
                ls[n * 2] += v00; lq2[n * 2] += v00 * v00;
                ls[n * 2 + 1] += v01; lq2[n * 2 + 1] += v01 * v01;
            }
            if (fB < nv) {
                *(float2*)&g_ybuf[((size_t)b * F + f0 + fB) * 64 + c0] = make_float2(v10, v11);
                ls[n * 2] += v10; lq2[n * 2] += v10 * v10;
                ls[n * 2 + 1] += v11; lq2[n * 2 + 1] += v11 * v11;
            }
        }
    }
    __syncthreads();   // all warps done with A smem before reuse as reduction space
    float* redS = (float*)(smc);            // [32][64]
    float* redQ = (float*)(smc + 8192);
    int row = warp * 8 + r;
#pragma unroll
    for (int n = 0; n < 8; n++) {
        redS[row * 64 + n * 8 + 2 * c] = ls[n * 2];
        redS[row * 64 + n * 8 + 2 * c + 1] = ls[n * 2 + 1];
        redQ[row * 64 + n * 8 + 2 * c] = lq2[n * 2];
        redQ[row * 64 + n * 8 + 2 * c + 1] = lq2[n * 2 + 1];
    }
    __syncthreads();
    if (t < 64) {
        float s = 0.f, q2 = 0.f;
#pragma unroll 8
        for (int i = 0; i < 32; i++) { s += redS[i * 64 + t]; q2 += redQ[i * 64 + t]; }
        int bid = blockIdx.y * gridDim.x + blockIdx.x;
        g_psum[bid * 64 + t] = s;
        g_psumsq[bid * 64 + t] = q2;
    }
}

// ---------------- reduction level 1: nblk partial rows -> 64 rows ----------------
__global__ void k_red1(int nblk, int rpb) {
    __shared__ float sS[4][64], sQ[4][64];
    int t = threadIdx.x;
    int c = t & 63, sl = t >> 6;
    int r0 = blockIdx.x * rpb;
    int r1 = r0 + rpb; if (r1 > nblk) r1 = nblk;
    float s = 0.f, q = 0.f;
    for (int i = r0 + sl; i < r1; i += 4) {
        s += g_psum[i * 64 + c];
        q += g_psumsq[i * 64 + c];
    }
    sS[sl][c] = s; sQ[sl][c] = q;
    __syncthreads();
    if (t < 64) {
        g_p2S[blockIdx.x * 64 + t] = sS[0][t] + sS[1][t] + sS[2][t] + sS[3][t];
        g_p2Q[blockIdx.x * 64 + t] = sQ[0][t] + sQ[1][t] + sQ[2][t] + sQ[3][t];
    }
}

// ---------------- apply with fused coefficient computation ----------------
__global__ __launch_bounds__(256) void k_applyc(const float* __restrict__ gamma,
                                                const float* __restrict__ beta,
                                                float invN, int res, int nvec) {
    __shared__ float sS[4][64], sQ[4][64];
    __shared__ float cA[64], cS[64];
    int t = threadIdx.x;
    int c = t & 63, sl = t >> 6;
    float s = 0.f, q = 0.f;
#pragma unroll
    for (int i = sl; i < 64; i += 4) {
        s += g_p2S[i * 64 + c];
        q += g_p2Q[i * 64 + c];
    }
    sS[sl][c] = s; sQ[sl][c] = q;
    __syncthreads();
    if (t < 64) {
        float ss = sS[0][t] + sS[1][t] + sS[2][t] + sS[3][t];
        float qq = sQ[0][t] + sQ[1][t] + sQ[2][t] + sQ[3][t];
        float m = ss * invN;
        float var = qq * invN - m * m;
        float rstd = rsqrtf(var + 1e-5f);
        float a = gamma[t] * rstd;
        cA[t] = a;
        cS[t] = beta[t] - m * a;
    }
    __syncthreads();
#pragma unroll
    for (int it = 0; it < 8; it++) {
        int i = (blockIdx.x * 8 + it) * 256 + t;
        if (i >= nvec) break;
        int c4 = i & 15;
        float4 a = *(const float4*)&cA[c4 * 4];
        float4 sh = *(const float4*)&cS[c4 * 4];
        float4 yv = ((const float4*)g_ybuf)[i];
        float4 o;
        o.x = a.x * yv.x + sh.x; o.y = a.y * yv.y + sh.y;
        o.z = a.z * yv.z + sh.z; o.w = a.w * yv.w + sh.w;
        if (res) {
            float4 xv = ((const float4*)g_xbuf)[i];
            o.x += xv.x; o.y += xv.y; o.z += xv.z; o.w += xv.w;
        }
        o.x = lrelu(o.x); o.y = lrelu(o.y); o.z = lrelu(o.z); o.w = lrelu(o.w);
        ((float4*)g_xbuf)[i] = o;
    }
}

// ---------------- coef finalize (stage 2 only) ----------------
__global__ void k_coef(const float* __restrict__ gamma,
                       const float* __restrict__ beta, int stage, float invN) {
    __shared__ float sS[4][64], sQ[4][64];
    int t = threadIdx.x;
    int c = t & 63, sl = t >> 6;
    float s = 0.f, q = 0.f;
#pragma unroll
    for (int i = sl; i < 64; i += 4) {
        s += g_p2S[i * 64 + c];
        q += g_p2Q[i * 64 + c];
    }
    sS[sl][c] = s; sQ[sl][c] = q;
    __syncthreads();
    if (t < 64) {
        float ss = sS[0][t] + sS[1][t] + sS[2][t] + sS[3][t];
        float qq = sQ[0][t] + sQ[1][t] + sQ[2][t] + sQ[3][t];
        float m = ss * invN;
        float var = qq * invN - m * m;
        float rstd = rsqrtf(var + 1e-5f);
        float a = gamma[t] * rstd;
        g_coefA[stage * 64 + t] = a;
        g_coefS[stage * 64 + t] = beta[t] - m * a;
    }
}

// ---------------- final apply + transpose to [B,O,F] ----------------
__global__ void k_apply_out(float* __restrict__ out, int F) {
    __shared__ float sm[32][33];
    int b = blockIdx.z;
    int o0 = blockIdx.y * 32;
    int f0 = blockIdx.x * 32;
    int tx = threadIdx.x, ty = threadIdx.y;
#pragma unroll
    for (int r = 0; r < 4; r++) {
        int f = f0 + ty + r * 8;
        int o = o0 + tx;
        float v = 0.f;
        if (f < F) {
            float a = g_coefA[2 * 64 + o], s = g_coefS[2 * 64 + o];
            size_t idx = ((size_t)b * F + f) * 64 + o;
            v = lrelu(a * g_ybuf[idx] + s + g_xbuf[idx]);
        }
        sm[ty + r * 8][tx] = v;
    }
    __syncthreads();
#pragma unroll
    for (int r = 0; r < 4; r++) {
        int o = o0 + ty + r * 8;
        int f = f0 + tx;
        if (f < F) out[((size_t)b * 64 + o) * F + f] = sm[tx][ty + r * 8];
    }
}

// ---------------- host launcher ----------------
extern "C" void kernel_launch(void* const* d_in, const int* in_sizes, int n_in,
                              void* d_out, int out_size) {
    const float* fe  = (const float*)d_in[0];
    const int*   gm  = (const int*)d_in[1];
    const float* w1  = (const float*)d_in[2];
    const float* b1  = (const float*)d_in[3];
    const float* w2a = (const float*)d_in[4];
    const float* b2a = (const float*)d_in[5];
    const float* w2b = (const float*)d_in[6];
    const float* b2b = (const float*)d_in[7];
    const float* g0  = (const float*)d_in[8];
    const float* be0 = (const float*)d_in[9];
    const float* g1  = (const float*)d_in[10];
    const float* be1 = (const float*)d_in[11];
    const float* g2  = (const float*)d_in[12];
    const float* be2 = (const float*)d_in[13];

    const int B = 4;
    const int F = in_sizes[1] / (3 * B);      // 50000
    const int Cin = in_sizes[0] / (B * F);    // 32

    const int SH = 34560;
    cudaFuncSetAttribute(k_conv<32>, cudaFuncAttributeMaxDynamicSharedMemorySize, SH);
    cudaFuncSetAttribute(k_conv<64>, cudaFuncAttributeMaxDynamicSharedMemorySize, SH);

    dim3 tb(32, 8);
    int ftiles32 = (F + 31) / 32;
    int fb = (F + 127) / 128;
    int nblk = fb * B;
    int rpb = (nblk + 63) / 64;
    float invN = 1.0f / (float)(B * F);
    int nvec = B * F * 16;
    int apb = (nvec + 2047) / 2048;
    int K1 = 4 * Cin;

    // launch order: conv<32> is my 4th launch -> captured by ncu
    k_wprep_all<<<(K1 * 64 + 32768 + 255) / 256, 256>>>(w1, w2a, w2b, K1);   // 1
    k_transpose<<<dim3(ftiles32, 1, 2), tb>>>(fe, Cin, F, 0);                // 2
    k_transpose<<<dim3(ftiles32, 1, 2), tb>>>(fe, Cin, F, 2);                // 3

    // stage 0
    k_conv<32><<<dim3(fb, B), 128, SH>>>(gm, 0, b1, F);                      // 4 <- ncu
    k_red1<<<64, 256>>>(nblk, rpb);
    k_applyc<<<apb, 256>>>(g0, be0, invN, 0, nvec);

    // stage 1 (residual)
    k_conv<64><<<dim3(fb, B), 128, SH>>>(gm, 1, b2a, F);
    k_red1<<<64, 256>>>(nblk, rpb);
    k_applyc<<<apb, 256>>>(g1, be1, invN, 1, nvec);

    // stage 2 (residual, fused final transpose)
    k_conv<64><<<dim3(fb, B), 128, SH>>>(gm, 2, b2b, F);
    k_red1<<<64, 256>>>(nblk, rpb);
    k_coef<<<1, 256>>>(g2, be2, 2, invN);
    k_apply_out<<<dim3(ftiles32, 2, B), tb>>>((float*)d_out, F);
}